// round 13
// baseline (speedup 1.0000x reference)
#include <cuda_runtime.h>
#include <cuda_fp16.h>
#include <cstdint>
#include <cstddef>

// ---------------------------------------------------------------------------
// NeuralODE Dopri5. GEMMs: mma.sync m16n8k16 FP16 (2xFP16 split: A=Ah+Al,
// W=Wh+Wl; Ah·Wh + Ah·Wl + Al·Wh, fp32 accum). BK=64, triple-buffered smem,
// 2-stage lookahead, ldmatrix fragments. NEW: Programmatic Dependent Launch —
// W prefetch runs BEFORE cudaGridDependencySynchronize, overlapping the
// previous kernel's epilogue; trigger fires after our mainloop.
// RK combine fused into layer-3 epilogue. 18 launches per RK step.
// ---------------------------------------------------------------------------

#define BB 1024
#define DD 256
#define HH 512
#define N_STEPS 40
#define HSTEP 0.25f

__device__ float g_y   [BB * DD];
__device__ float g_ycmb[BB * DD];
__device__ float g_k [6][BB * DD];
__device__ float g_h1[BB * HH];
__device__ float g_h2[BB * HH];
__device__ __half g_W1hi[HH * DD], g_W1lo[HH * DD];
__device__ __half g_W2hi[HH * HH], g_W2lo[HH * HH];
__device__ __half g_W3hi[DD * HH], g_W3lo[DD * HH];

struct Epi {
    const float* yin;
    const float* ks[4];
    float        cks[4];
    int          nks;
    float        cself;
    float*       aux;
    float*       emit;
    int          t;
};

// ----------------------------- helpers -------------------------------------
__device__ __forceinline__ uint32_t smem_u32(const void* p) {
    uint32_t a;
    asm("{ .reg .u64 t; cvta.to.shared.u64 t, %1; cvt.u32.u64 %0, t; }"
        : "=r"(a) : "l"(p));
    return a;
}
__device__ __forceinline__ uint32_t packh2(__half a, __half b) {
    __half2 t = __halves2half2(a, b);
    return *reinterpret_cast<uint32_t*>(&t);
}
__device__ __forceinline__ void sts128(uint32_t a, uint32_t x, uint32_t y,
                                       uint32_t z, uint32_t w) {
    asm volatile("st.shared.v4.b32 [%0], {%1,%2,%3,%4};"
                 :: "r"(a), "r"(x), "r"(y), "r"(z), "r"(w) : "memory");
}
__device__ __forceinline__ void cp16(uint32_t d, const void* s) {
    asm volatile("cp.async.cg.shared.global [%0], [%1], 16;"
                 :: "r"(d), "l"(s) : "memory");
}
__device__ __forceinline__ void cp_commit() {
    asm volatile("cp.async.commit_group;" ::: "memory");
}
__device__ __forceinline__ void cp_wait1() {
    asm volatile("cp.async.wait_group 1;" ::: "memory");
}
__device__ __forceinline__ void ldm4(uint32_t* r, uint32_t addr) {
    asm volatile("ldmatrix.sync.aligned.m8n8.x4.shared.b16 {%0,%1,%2,%3}, [%4];"
                 : "=r"(r[0]), "=r"(r[1]), "=r"(r[2]), "=r"(r[3]) : "r"(addr));
}
__device__ __forceinline__ void mma16(float* d, const uint32_t* a,
                                      uint32_t b0, uint32_t b1) {
    asm volatile(
        "mma.sync.aligned.m16n8k16.row.col.f32.f16.f16.f32 "
        "{%0,%1,%2,%3}, {%4,%5,%6,%7}, {%8,%9}, {%0,%1,%2,%3};"
        : "+f"(d[0]), "+f"(d[1]), "+f"(d[2]), "+f"(d[3])
        : "r"(a[0]), "r"(a[1]), "r"(a[2]), "r"(a[3]), "r"(b0), "r"(b1));
}

// ---------------------------------------------------------------------------
// GEMM: C[M,N] = act(A @ W^T + bias). 256 threads, warp grid 2(M) x 4(N),
// warp tile (16*MT) x 16, CTA tile (32*MT) x 64. BK=64 (4 k16-slices/stage),
// 3 smem buffers, 2-stage lookahead. Smem rows 128B (64 fp16), XOR swizzle
// 16B-chunk ^= (row&7). Stage: Ahi[AB] Alo[AB] Whi[8192] Wlo[8192].
// PDL: W prologue issued pre-sync; A loads post-sync; trigger post-mainloop.
// MODE 0: relu fp32 store. MODE 1: linear store + fused RK-combine epilogue.
// ---------------------------------------------------------------------------
template<int MT, int MODE>
__global__ __launch_bounds__(256, 1)
void gemm_tc(const float* __restrict__ A,
             const __half* __restrict__ Whi, const __half* __restrict__ Wlo,
             const float* __restrict__ bias, float* __restrict__ C,
             int K, int N, Epi ep)
{
    constexpr int BM = 32 * MT;
    constexpr int TPR = 256 / BM;
    constexpr int AQ  = MT;
    constexpr uint32_t AB = (uint32_t)BM * 128;
    constexpr uint32_t WB = 64 * 128;
    constexpr uint32_t WOFFS = 2 * AB;
    constexpr uint32_t STRIDE = 2 * AB + 2 * WB;

    extern __shared__ float smem[];
    const uint32_t sb = smem_u32(smem);
    const int tid  = threadIdx.x;
    const int warp = tid >> 5, lane = tid & 31;
    const int wM = warp >> 2, wN = warp & 3;
    const int g = lane >> 2, c = lane & 3;
    const int m0 = blockIdx.y * BM, n0 = blockIdx.x * 64;

    const int arw  = tid / TPR;
    const int akc0 = (tid % TPR) * AQ;
    const int wrw  = tid >> 2;
    const int wkc0 = (tid & 3) * 2;

    const int quad = lane >> 3, l8 = lane & 7;
    const uint32_t aqs = (uint32_t)(quad >> 1);
    const uint32_t bqs = (uint32_t)(quad & 1);
    uint32_t aoffA[MT];
    #pragma unroll
    for (int i = 0; i < MT; i++)
        aoffA[i] = (uint32_t)(wM * 16 * MT + i * 16 + ((quad & 1) << 3) + l8) * 128;
    const uint32_t boffB = WOFFS
        + (uint32_t)(wN * 16 + ((quad >> 1) << 3) + l8) * 128;

    const int S = K >> 6;
    float4 pa[AQ][2];

    auto ldA = [&](int s) {
        #pragma unroll
        for (int q = 0; q < AQ; q++) {
            const float* p = A + (size_t)(m0 + arw) * K + (s << 6)
                           + (akc0 + q) * 8;
            pa[q][0] = *(const float4*)p;
            pa[q][1] = *(const float4*)(p + 4);
        }
    };
    auto stA = [&](int buf) {
        #pragma unroll
        for (int q = 0; q < AQ; q++) {
            const int kc = akc0 + q;
            const uint32_t d = sb + (uint32_t)buf * STRIDE
                             + (uint32_t)arw * 128
                             + (uint32_t)((kc ^ (arw & 7)) << 4);
            const float* f = (const float*)&pa[q][0];
            uint32_t hi[4], lo[4];
            #pragma unroll
            for (int e = 0; e < 4; e++) {
                float f0 = f[2 * e], f1 = f[2 * e + 1];
                __half h0 = __float2half_rn(f0), h1 = __float2half_rn(f1);
                hi[e] = packh2(h0, h1);
                __half r0 = __float2half_rn(f0 - __half2float(h0));
                __half r1 = __float2half_rn(f1 - __half2float(h1));
                lo[e] = packh2(r0, r1);
            }
            sts128(d,      hi[0], hi[1], hi[2], hi[3]);
            sts128(d + AB, lo[0], lo[1], lo[2], lo[3]);
        }
    };
    auto cpW = [&](int s, int buf) {
        #pragma unroll
        for (int q = 0; q < 2; q++) {
            const int kc = wkc0 + q;
            const size_t off = (size_t)(n0 + wrw) * K + (s << 6) + kc * 8;
            const uint32_t d = sb + (uint32_t)buf * STRIDE + WOFFS
                             + (uint32_t)wrw * 128
                             + (uint32_t)((kc ^ (wrw & 7)) << 4);
            cp16(d,      Whi + off);
            cp16(d + WB, Wlo + off);
        }
    };

    float acc[MT][2][4];
    #pragma unroll
    for (int i = 0; i < MT; i++)
        #pragma unroll
        for (int nt = 0; nt < 2; nt++)
            #pragma unroll
            for (int q = 0; q < 4; q++) acc[i][nt][q] = 0.0f;

    // ---- PDL preamble: W is independent of the predecessor's output ----
    cpW(0, 0); cp_commit();
    cpW(1, 1); cp_commit();

    // Wait for the predecessor kernel's stores (A operand) to be visible.
    cudaGridDependencySynchronize();

    // ---- A prologue (depends on predecessor) ----
    ldA(0);
    stA(0);
    ldA(1);

    int cur = 0, nxt = 1, nx2 = 2;

    for (int s = 0; s < S; s++) {
        cp_wait1();
        __syncthreads();

        if (s + 1 < S) stA(nxt);
        if (s + 2 < S) { ldA(s + 2); cpW(s + 2, nx2); }
        cp_commit();

        const uint32_t base = sb + (uint32_t)cur * STRIDE;
        uint32_t ah[2][MT][4], al[2][MT][4], bh[2][4], bl[2][4];

        auto ldfrag = [&](int j, int fb) {
            const uint32_t colA = (uint32_t)(((2 * j + aqs) ^ l8) << 4);
            const uint32_t colB = (uint32_t)(((2 * j + bqs) ^ l8) << 4);
            #pragma unroll
            for (int i = 0; i < MT; i++) {
                ldm4(ah[fb][i], base + aoffA[i] + colA);
                ldm4(al[fb][i], base + AB + aoffA[i] + colA);
            }
            ldm4(bh[fb], base + boffB + colB);
            ldm4(bl[fb], base + WB + boffB + colB);
        };

        ldfrag(0, 0);
        #pragma unroll
        for (int j = 0; j < 4; j++) {
            const int fb = j & 1;
            if (j < 3) ldfrag(j + 1, fb ^ 1);
            #pragma unroll
            for (int i = 0; i < MT; i++) {
                mma16(acc[i][0], ah[fb][i], bh[fb][0], bh[fb][1]);
                mma16(acc[i][1], ah[fb][i], bh[fb][2], bh[fb][3]);
                mma16(acc[i][0], ah[fb][i], bl[fb][0], bl[fb][1]);
                mma16(acc[i][1], ah[fb][i], bl[fb][2], bl[fb][3]);
                mma16(acc[i][0], al[fb][i], bh[fb][0], bh[fb][1]);
                mma16(acc[i][1], al[fb][i], bh[fb][2], bh[fb][3]);
            }
        }

        const int tmp = cur; cur = nxt; nxt = nx2; nx2 = tmp;
    }

    // Allow the successor kernel to launch and run its W preamble while we
    // finish the epilogue (it blocks in cudaGridDependencySynchronize until
    // all our stores below are complete and visible).
    cudaTriggerProgrammaticLaunchCompletion();

    // ---- epilogue ----
    #pragma unroll
    for (int i = 0; i < MT; i++) {
        #pragma unroll
        for (int nt = 0; nt < 2; nt++) {
            const int col  = n0 + wN * 16 + nt * 8 + 2 * c;
            const float b0v = bias[col], b1v = bias[col + 1];
            const int row0 = m0 + wM * 16 * MT + i * 16 + g;
            #pragma unroll
            for (int hh = 0; hh < 2; hh++) {
                const int row = row0 + 8 * hh;
                float v0 = acc[i][nt][2 * hh + 0] + b0v;
                float v1 = acc[i][nt][2 * hh + 1] + b1v;
                const size_t idx = (size_t)row * N + col;
                if (MODE == 0) {
                    v0 = fmaxf(v0, 0.0f); v1 = fmaxf(v1, 0.0f);
                    *(float2*)(C + idx) = make_float2(v0, v1);
                } else {
                    *(float2*)(C + idx) = make_float2(v0, v1);
                    float a0 = ep.yin[idx]     + ep.cself * v0;
                    float a1 = ep.yin[idx + 1] + ep.cself * v1;
                    for (int t = 0; t < ep.nks; t++) {
                        a0 += ep.cks[t] * ep.ks[t][idx];
                        a1 += ep.cks[t] * ep.ks[t][idx + 1];
                    }
                    *(float2*)(ep.aux + idx) = make_float2(a0, a1);
                    if (ep.emit) {
                        const size_t o = (size_t)row * (10 * DD) + (size_t)ep.t * DD + col;
                        *(float2*)(ep.emit + o) = make_float2(a0, a1);
                    }
                }
            }
        }
    }
}

// Split W into fp16 hi/lo parts
__global__ void wsplit_kernel(const float* __restrict__ W,
                              __half* __restrict__ hi, __half* __restrict__ lo,
                              int n)
{
    int i = blockIdx.x * blockDim.x + threadIdx.x;
    if (i < n) {
        float x = W[i];
        __half h = __float2half_rn(x);
        hi[i] = h;
        lo[i] = __float2half_rn(x - __half2float(h));
    }
}

extern "C" void kernel_launch(void* const* d_in, const int* in_sizes, int n_in,
                              void* d_out, int out_size)
{
    (void)in_sizes; (void)n_in; (void)out_size;
    const float* x0 = (const float*)d_in[0];
    // d_in[1] is T (int32, always 11) — baked into the graph.
    const float* W1 = (const float*)d_in[2];
    const float* b1 = (const float*)d_in[3];
    const float* W2 = (const float*)d_in[4];
    const float* b2 = (const float*)d_in[5];
    const float* W3 = (const float*)d_in[6];
    const float* b3 = (const float*)d_in[7];
    float* out = (float*)d_out;

    float *y, *ycmb, *h1, *h2, *kbase;
    __half *w1h, *w1l, *w2h, *w2l, *w3h, *w3l;
    cudaGetSymbolAddress((void**)&y,     g_y);
    cudaGetSymbolAddress((void**)&ycmb,  g_ycmb);
    cudaGetSymbolAddress((void**)&h1,    g_h1);
    cudaGetSymbolAddress((void**)&h2,    g_h2);
    cudaGetSymbolAddress((void**)&kbase, g_k);
    cudaGetSymbolAddress((void**)&w1h,   g_W1hi);
    cudaGetSymbolAddress((void**)&w1l,   g_W1lo);
    cudaGetSymbolAddress((void**)&w2h,   g_W2hi);
    cudaGetSymbolAddress((void**)&w2l,   g_W2lo);
    cudaGetSymbolAddress((void**)&w3h,   g_W3hi);
    cudaGetSymbolAddress((void**)&w3l,   g_W3lo);
    float* k[6];
    for (int j = 0; j < 6; j++) k[j] = kbase + (size_t)j * BB * DD;

    const int SM12 = 3 * (2 * 64 * 128 + 2 * 64 * 128);   // MT=2: 98304
    const int SM3  = 3 * (2 * 32 * 128 + 2 * 64 * 128);   // MT=1: 73728
    cudaFuncSetAttribute((const void*)&gemm_tc<2, 0>,
                         cudaFuncAttributeMaxDynamicSharedMemorySize, SM12);
    cudaFuncSetAttribute((const void*)&gemm_tc<1, 1>,
                         cudaFuncAttributeMaxDynamicSharedMemorySize, SM3);

    // y = x0[:,0,:]
    cudaMemcpyAsync(y, x0, sizeof(float) * BB * DD, cudaMemcpyDeviceToDevice);

    wsplit_kernel<<<(HH * DD + 255) / 256, 256>>>(W1, w1h, w1l, HH * DD);
    wsplit_kernel<<<(HH * HH + 255) / 256, 256>>>(W2, w2h, w2l, HH * HH);
    wsplit_kernel<<<(DD * HH + 255) / 256, 256>>>(W3, w3h, w3l, DD * HH);

    // Dopri5 tableau
    const double A2[] = {1.0/5.0};
    const double A3[] = {3.0/40.0, 9.0/40.0};
    const double A4[] = {44.0/45.0, -56.0/15.0, 32.0/9.0};
    const double A5[] = {19372.0/6561.0, -25360.0/2187.0, 64448.0/6561.0, -212.0/729.0};
    const double A6[] = {9017.0/3168.0, -355.0/33.0, 46732.0/5247.0, 49.0/176.0, -5103.0/18656.0};
    const double* Arows[5] = {A2, A3, A4, A5, A6};

    const dim3 grd1(HH / 64, BB / 64);   // 128 CTAs
    const dim3 grd3(DD / 64, BB / 32);   // 128 CTAs

    // PDL launch plumbing
    cudaLaunchAttribute pdlAttr[1];
    pdlAttr[0].id = cudaLaunchAttributeProgrammaticStreamSerialization;
    pdlAttr[0].val.programmaticStreamSerializationAllowed = 1;

    cudaLaunchConfig_t cfg12 = {};
    cfg12.gridDim = grd1; cfg12.blockDim = dim3(256, 1, 1);
    cfg12.dynamicSmemBytes = SM12; cfg12.stream = 0;
    cfg12.attrs = pdlAttr; cfg12.numAttrs = 1;

    cudaLaunchConfig_t cfg3 = {};
    cfg3.gridDim = grd3; cfg3.blockDim = dim3(256, 1, 1);
    cfg3.dynamicSmemBytes = SM3; cfg3.stream = 0;
    cfg3.attrs = pdlAttr; cfg3.numAttrs = 1;

    Epi enone = {};

    for (int step = 0; step < N_STEPS; step++) {
        for (int s = 0; s < 6; s++) {
            const float* Ain = (s == 0) ? y : ycmb;
            cudaLaunchKernelEx(&cfg12, gemm_tc<2, 0>,
                               Ain, (const __half*)w1h, (const __half*)w1l,
                               b1, h1, DD, HH, enone);
            cudaLaunchKernelEx(&cfg12, gemm_tc<2, 0>,
                               (const float*)h1, (const __half*)w2h,
                               (const __half*)w2l, b2, h2, HH, HH, enone);

            Epi ep = {};
            ep.yin = y;
            if (s < 5) {
                const double* row = Arows[s];
                ep.nks = s;
                for (int j = 0; j < s; j++) {
                    ep.ks[j]  = k[j];
                    ep.cks[j] = (float)((double)HSTEP * row[j]);
                }
                ep.cself = (float)((double)HSTEP * row[s]);
                ep.aux   = ycmb;
                ep.emit  = nullptr;
                ep.t     = 0;
            } else {
                ep.nks = 4;
                ep.ks[0] = k[0]; ep.cks[0] = (float)((double)HSTEP * (35.0 / 384.0));
                ep.ks[1] = k[2]; ep.cks[1] = (float)((double)HSTEP * (500.0 / 1113.0));
                ep.ks[2] = k[3]; ep.cks[2] = (float)((double)HSTEP * (125.0 / 192.0));
                ep.ks[3] = k[4]; ep.cks[3] = (float)((double)HSTEP * (-2187.0 / 6784.0));
                ep.cself = (float)((double)HSTEP * (11.0 / 84.0));
                ep.aux   = y;
                ep.emit  = ((step & 3) == 3) ? out : nullptr;
                ep.t     = step >> 2;
            }
            cudaLaunchKernelEx(&cfg3, gemm_tc<1, 1>,
                               (const float*)h2, (const __half*)w3h,
                               (const __half*)w3l, b3, k[s], HH, DD, ep);
        }
    }
}

// round 14
// speedup vs baseline: 1.3417x; 1.3417x over previous
#include <cuda_runtime.h>
#include <cuda_fp16.h>
#include <cstdint>
#include <cstddef>

// ---------------------------------------------------------------------------
// NeuralODE Dopri5. GEMMs: mma.sync m16n8k16 FP16 (2xFP16 split: X=Xh+Xl;
// Ah·Wh + Ah·Wl + Al·Wh, fp32 accum). ALL operands pre-split fp16 hi/lo in
// gmem (same bytes as fp32) -> full cp.async 4-stage pipeline, wait_group 2,
// one barrier per stage, ldmatrix fragments. Activations are split in the
// producer's epilogue; RK combine fused into layer-3 epilogue.
// ---------------------------------------------------------------------------

#define BB 1024
#define DD 256
#define HH 512
#define N_STEPS 40
#define HSTEP 0.25f

__device__ float  g_y [BB * DD];          // fp32 RK state
__device__ float  g_k [6][BB * DD];       // fp32 stage derivatives
__device__ __half g_yh  [BB * DD], g_yl  [BB * DD];
__device__ __half g_cmh [BB * DD], g_cml [BB * DD];
__device__ __half g_h1h [BB * HH], g_h1l [BB * HH];
__device__ __half g_h2h [BB * HH], g_h2l [BB * HH];
__device__ __half g_W1hi[HH * DD], g_W1lo[HH * DD];
__device__ __half g_W2hi[HH * HH], g_W2lo[HH * HH];
__device__ __half g_W3hi[DD * HH], g_W3lo[DD * HH];

struct Epi {
    const float* yin;
    const float* ks[4];
    float        cks[4];
    int          nks;
    float        cself;
    __half*      auxh;
    __half*      auxl;
    float*       auxfp;
    float*       emit;
    int          t;
};

// ----------------------------- helpers -------------------------------------
__device__ __forceinline__ uint32_t smem_u32(const void* p) {
    uint32_t a;
    asm("{ .reg .u64 t; cvta.to.shared.u64 t, %1; cvt.u32.u64 %0, t; }"
        : "=r"(a) : "l"(p));
    return a;
}
__device__ __forceinline__ uint32_t packh2(__half a, __half b) {
    __half2 t = __halves2half2(a, b);
    return *reinterpret_cast<uint32_t*>(&t);
}
__device__ __forceinline__ void cp16(uint32_t d, const void* s) {
    asm volatile("cp.async.cg.shared.global [%0], [%1], 16;"
                 :: "r"(d), "l"(s) : "memory");
}
__device__ __forceinline__ void cp_commit() {
    asm volatile("cp.async.commit_group;" ::: "memory");
}
__device__ __forceinline__ void cp_wait2() {
    asm volatile("cp.async.wait_group 2;" ::: "memory");
}
__device__ __forceinline__ void ldm4(uint32_t* r, uint32_t addr) {
    asm volatile("ldmatrix.sync.aligned.m8n8.x4.shared.b16 {%0,%1,%2,%3}, [%4];"
                 : "=r"(r[0]), "=r"(r[1]), "=r"(r[2]), "=r"(r[3]) : "r"(addr));
}
__device__ __forceinline__ void mma16(float* d, const uint32_t* a,
                                      uint32_t b0, uint32_t b1) {
    asm volatile(
        "mma.sync.aligned.m16n8k16.row.col.f32.f16.f16.f32 "
        "{%0,%1,%2,%3}, {%4,%5,%6,%7}, {%8,%9}, {%0,%1,%2,%3};"
        : "+f"(d[0]), "+f"(d[1]), "+f"(d[2]), "+f"(d[3])
        : "r"(a[0]), "r"(a[1]), "r"(a[2]), "r"(a[3]), "r"(b0), "r"(b1));
}

// ---------------------------------------------------------------------------
// GEMM: out = act(A @ W^T + bias). 256 threads, warp grid 2(M) x 4(N),
// warp tile (16*MT) x 16, CTA tile (32*MT) x 64. BK=64 (4 k16-slices/stage).
// 4 smem stage buffers, all operands via cp.async (A and W both fp16 hi/lo in
// gmem), wait_group 2, one __syncthreads + one commit per stage.
// Smem rows 128B (64 fp16), XOR swizzle: 16B-chunk ^= (row&7).
// Stage: Ahi[AB] Alo[AB] Whi[8192] Wlo[8192], AB = BM*128.
// MODE 0: relu, outputs split fp16 (Chi/Clo).
// MODE 1: fp32 store to C + fused RK combine -> auxh/auxl (+fp32/emit).
// ---------------------------------------------------------------------------
template<int MT, int MODE>
__global__ __launch_bounds__(256, 1)
void gemm_tc(const __half* __restrict__ Ahi, const __half* __restrict__ Alo,
             const __half* __restrict__ Whi, const __half* __restrict__ Wlo,
             const float* __restrict__ bias,
             float* __restrict__ C, __half* __restrict__ Chi,
             __half* __restrict__ Clo, int K, int N, Epi ep)
{
    constexpr int BM  = 32 * MT;
    constexpr int TPR = 256 / BM;                 // threads per A row
    constexpr int CPT = 8 / TPR;                  // A chunks per thread/part
    constexpr uint32_t AB = (uint32_t)BM * 128;
    constexpr uint32_t WB = 64 * 128;
    constexpr uint32_t WOFFS = 2 * AB;
    constexpr uint32_t STRIDE = 2 * AB + 2 * WB;

    extern __shared__ float smem[];
    const uint32_t sb = smem_u32(smem);
    const int tid  = threadIdx.x;
    const int warp = tid >> 5, lane = tid & 31;
    const int wM = warp >> 2, wN = warp & 3;
    const int g = lane >> 2, c = lane & 3;
    const int m0 = blockIdx.y * BM, n0 = blockIdx.x * 64;

    // loader geometry
    const int arw  = tid / TPR;
    const int akc0 = (tid % TPR) * CPT;
    const int wrw  = tid >> 2;
    const int wkc0 = (tid & 3) * 2;

    // ldmatrix geometry
    const int quad = lane >> 3, l8 = lane & 7;
    const uint32_t aqs = (uint32_t)(quad >> 1);
    const uint32_t bqs = (uint32_t)(quad & 1);
    uint32_t aoffA[MT];
    #pragma unroll
    for (int i = 0; i < MT; i++)
        aoffA[i] = (uint32_t)(wM * 16 * MT + i * 16 + ((quad & 1) << 3) + l8) * 128;
    const uint32_t boffB = WOFFS
        + (uint32_t)(wN * 16 + ((quad >> 1) << 3) + l8) * 128;

    const int S = K >> 6;

    auto cpStage = [&](int s, int buf) {
        const uint32_t b0 = sb + (uint32_t)buf * STRIDE;
        #pragma unroll
        for (int q = 0; q < CPT; q++) {
            const int kc = akc0 + q;
            const size_t off = (size_t)(m0 + arw) * K + (s << 6) + kc * 8;
            const uint32_t d = b0 + (uint32_t)arw * 128
                             + (uint32_t)((kc ^ (arw & 7)) << 4);
            cp16(d,      Ahi + off);
            cp16(d + AB, Alo + off);
        }
        #pragma unroll
        for (int q = 0; q < 2; q++) {
            const int kc = wkc0 + q;
            const size_t off = (size_t)(n0 + wrw) * K + (s << 6) + kc * 8;
            const uint32_t d = b0 + WOFFS + (uint32_t)wrw * 128
                             + (uint32_t)((kc ^ (wrw & 7)) << 4);
            cp16(d,      Whi + off);
            cp16(d + WB, Wlo + off);
        }
        cp_commit();
    };

    float acc[MT][2][4];
    #pragma unroll
    for (int i = 0; i < MT; i++)
        #pragma unroll
        for (int nt = 0; nt < 2; nt++)
            #pragma unroll
            for (int q = 0; q < 4; q++) acc[i][nt][q] = 0.0f;

    // prologue: 3 stages in flight
    cpStage(0, 0);
    cpStage(1, 1);
    cpStage(2, 2);

    for (int s = 0; s < S; s++) {
        cp_wait2();              // stage s resident
        __syncthreads();         // everyone done reading buffer (s-1)&3
        if (s + 3 < S) cpStage(s + 3, (s + 3) & 3);
        else           cp_commit();      // keep group arithmetic uniform

        const uint32_t base = sb + (uint32_t)(s & 3) * STRIDE;
        uint32_t ah[2][MT][4], al[2][MT][4], bh[2][4], bl[2][4];

        auto ldfrag = [&](int j, int fb) {
            const uint32_t colA = (uint32_t)(((2 * j + aqs) ^ l8) << 4);
            const uint32_t colB = (uint32_t)(((2 * j + bqs) ^ l8) << 4);
            #pragma unroll
            for (int i = 0; i < MT; i++) {
                ldm4(ah[fb][i], base + aoffA[i] + colA);
                ldm4(al[fb][i], base + AB + aoffA[i] + colA);
            }
            ldm4(bh[fb], base + boffB + colB);
            ldm4(bl[fb], base + WB + boffB + colB);
        };

        ldfrag(0, 0);
        #pragma unroll
        for (int j = 0; j < 4; j++) {
            const int fb = j & 1;
            if (j < 3) ldfrag(j + 1, fb ^ 1);
            #pragma unroll
            for (int i = 0; i < MT; i++) {
                mma16(acc[i][0], ah[fb][i], bh[fb][0], bh[fb][1]);
                mma16(acc[i][1], ah[fb][i], bh[fb][2], bh[fb][3]);
                mma16(acc[i][0], ah[fb][i], bl[fb][0], bl[fb][1]);
                mma16(acc[i][1], ah[fb][i], bl[fb][2], bl[fb][3]);
                mma16(acc[i][0], al[fb][i], bh[fb][0], bh[fb][1]);
                mma16(acc[i][1], al[fb][i], bh[fb][2], bh[fb][3]);
            }
        }
    }

    // ---- epilogue ----
    #pragma unroll
    for (int i = 0; i < MT; i++) {
        #pragma unroll
        for (int nt = 0; nt < 2; nt++) {
            const int col  = n0 + wN * 16 + nt * 8 + 2 * c;
            const float b0v = bias[col], b1v = bias[col + 1];
            const int row0 = m0 + wM * 16 * MT + i * 16 + g;
            #pragma unroll
            for (int hh = 0; hh < 2; hh++) {
                const int row = row0 + 8 * hh;
                float v0 = acc[i][nt][2 * hh + 0] + b0v;
                float v1 = acc[i][nt][2 * hh + 1] + b1v;
                const size_t idx = (size_t)row * N + col;
                if (MODE == 0) {
                    v0 = fmaxf(v0, 0.0f); v1 = fmaxf(v1, 0.0f);
                    __half h0 = __float2half_rn(v0), h1 = __float2half_rn(v1);
                    *reinterpret_cast<uint32_t*>(Chi + idx) = packh2(h0, h1);
                    *reinterpret_cast<uint32_t*>(Clo + idx) = packh2(
                        __float2half_rn(v0 - __half2float(h0)),
                        __float2half_rn(v1 - __half2float(h1)));
                } else {
                    *(float2*)(C + idx) = make_float2(v0, v1);
                    float a0 = ep.yin[idx]     + ep.cself * v0;
                    float a1 = ep.yin[idx + 1] + ep.cself * v1;
                    for (int t = 0; t < ep.nks; t++) {
                        a0 += ep.cks[t] * ep.ks[t][idx];
                        a1 += ep.cks[t] * ep.ks[t][idx + 1];
                    }
                    __half h0 = __float2half_rn(a0), h1 = __float2half_rn(a1);
                    *reinterpret_cast<uint32_t*>(ep.auxh + idx) = packh2(h0, h1);
                    *reinterpret_cast<uint32_t*>(ep.auxl + idx) = packh2(
                        __float2half_rn(a0 - __half2float(h0)),
                        __float2half_rn(a1 - __half2float(h1)));
                    if (ep.auxfp)
                        *(float2*)(ep.auxfp + idx) = make_float2(a0, a1);
                    if (ep.emit) {
                        const size_t o = (size_t)row * (10 * DD) + (size_t)ep.t * DD + col;
                        *(float2*)(ep.emit + o) = make_float2(a0, a1);
                    }
                }
            }
        }
    }
}

// Split fp32 X into fp16 hi/lo parts
__global__ void wsplit_kernel(const float* __restrict__ X,
                              __half* __restrict__ hi, __half* __restrict__ lo,
                              int n)
{
    int i = blockIdx.x * blockDim.x + threadIdx.x;
    if (i < n) {
        float x = X[i];
        __half h = __float2half_rn(x);
        hi[i] = h;
        lo[i] = __float2half_rn(x - __half2float(h));
    }
}

extern "C" void kernel_launch(void* const* d_in, const int* in_sizes, int n_in,
                              void* d_out, int out_size)
{
    (void)in_sizes; (void)n_in; (void)out_size;
    const float* x0 = (const float*)d_in[0];
    // d_in[1] is T (int32, always 11) — baked into the graph.
    const float* W1 = (const float*)d_in[2];
    const float* b1 = (const float*)d_in[3];
    const float* W2 = (const float*)d_in[4];
    const float* b2 = (const float*)d_in[5];
    const float* W3 = (const float*)d_in[6];
    const float* b3 = (const float*)d_in[7];
    float* out = (float*)d_out;

    float *y, *kbase;
    __half *yh, *yl, *cmh, *cml, *h1h, *h1l, *h2h, *h2l;
    __half *w1h, *w1l, *w2h, *w2l, *w3h, *w3l;
    cudaGetSymbolAddress((void**)&y,     g_y);
    cudaGetSymbolAddress((void**)&kbase, g_k);
    cudaGetSymbolAddress((void**)&yh,    g_yh);
    cudaGetSymbolAddress((void**)&yl,    g_yl);
    cudaGetSymbolAddress((void**)&cmh,   g_cmh);
    cudaGetSymbolAddress((void**)&cml,   g_cml);
    cudaGetSymbolAddress((void**)&h1h,   g_h1h);
    cudaGetSymbolAddress((void**)&h1l,   g_h1l);
    cudaGetSymbolAddress((void**)&h2h,   g_h2h);
    cudaGetSymbolAddress((void**)&h2l,   g_h2l);
    cudaGetSymbolAddress((void**)&w1h,   g_W1hi);
    cudaGetSymbolAddress((void**)&w1l,   g_W1lo);
    cudaGetSymbolAddress((void**)&w2h,   g_W2hi);
    cudaGetSymbolAddress((void**)&w2l,   g_W2lo);
    cudaGetSymbolAddress((void**)&w3h,   g_W3hi);
    cudaGetSymbolAddress((void**)&w3l,   g_W3lo);
    float* k[6];
    for (int j = 0; j < 6; j++) k[j] = (float*)kbase + (size_t)j * BB * DD;

    // 4 stage buffers of (2*AB + 2*WB)
    const int SM12 = 4 * (2 * 64 * 128 + 2 * 64 * 128);   // MT=2: 131072
    const int SM3  = 4 * (2 * 32 * 128 + 2 * 64 * 128);   // MT=1: 98304
    cudaFuncSetAttribute((const void*)&gemm_tc<2, 0>,
                         cudaFuncAttributeMaxDynamicSharedMemorySize, SM12);
    cudaFuncSetAttribute((const void*)&gemm_tc<1, 1>,
                         cudaFuncAttributeMaxDynamicSharedMemorySize, SM3);

    // y = x0[:,0,:]; split to fp16 hi/lo
    cudaMemcpyAsync(y, x0, sizeof(float) * BB * DD, cudaMemcpyDeviceToDevice);
    wsplit_kernel<<<(BB * DD + 255) / 256, 256>>>(x0, yh, yl, BB * DD);
    wsplit_kernel<<<(HH * DD + 255) / 256, 256>>>(W1, w1h, w1l, HH * DD);
    wsplit_kernel<<<(HH * HH + 255) / 256, 256>>>(W2, w2h, w2l, HH * HH);
    wsplit_kernel<<<(DD * HH + 255) / 256, 256>>>(W3, w3h, w3l, DD * HH);

    // Dopri5 tableau
    const double A2[] = {1.0/5.0};
    const double A3[] = {3.0/40.0, 9.0/40.0};
    const double A4[] = {44.0/45.0, -56.0/15.0, 32.0/9.0};
    const double A5[] = {19372.0/6561.0, -25360.0/2187.0, 64448.0/6561.0, -212.0/729.0};
    const double A6[] = {9017.0/3168.0, -355.0/33.0, 46732.0/5247.0, 49.0/176.0, -5103.0/18656.0};
    const double* Arows[5] = {A2, A3, A4, A5, A6};

    const dim3 grd1(HH / 64, BB / 64);   // 8 x 16 = 128 CTAs
    const dim3 grd3(DD / 64, BB / 32);   // 4 x 32 = 128 CTAs

    Epi enone = {};

    for (int step = 0; step < N_STEPS; step++) {
        for (int s = 0; s < 6; s++) {
            const __half* Ah = (s == 0) ? yh : cmh;
            const __half* Al = (s == 0) ? yl : cml;
            gemm_tc<2, 0><<<grd1, 256, SM12>>>(Ah, Al, w1h, w1l, b1,
                                               nullptr, h1h, h1l, DD, HH, enone);
            gemm_tc<2, 0><<<grd1, 256, SM12>>>(h1h, h1l, w2h, w2l, b2,
                                               nullptr, h2h, h2l, HH, HH, enone);

            Epi ep = {};
            ep.yin = y;
            if (s < 5) {
                const double* row = Arows[s];
                ep.nks = s;
                for (int j = 0; j < s; j++) {
                    ep.ks[j]  = k[j];
                    ep.cks[j] = (float)((double)HSTEP * row[j]);
                }
                ep.cself = (float)((double)HSTEP * row[s]);
                ep.auxh  = cmh;
                ep.auxl  = cml;
                ep.auxfp = nullptr;
                ep.emit  = nullptr;
                ep.t     = 0;
            } else {
                ep.nks = 4;
                ep.ks[0] = k[0]; ep.cks[0] = (float)((double)HSTEP * (35.0 / 384.0));
                ep.ks[1] = k[2]; ep.cks[1] = (float)((double)HSTEP * (500.0 / 1113.0));
                ep.ks[2] = k[3]; ep.cks[2] = (float)((double)HSTEP * (125.0 / 192.0));
                ep.ks[3] = k[4]; ep.cks[3] = (float)((double)HSTEP * (-2187.0 / 6784.0));
                ep.cself = (float)((double)HSTEP * (11.0 / 84.0));
                ep.auxh  = yh;
                ep.auxl  = yl;
                ep.auxfp = y;
                ep.emit  = ((step & 3) == 3) ? out : nullptr;
                ep.t     = step >> 2;
            }
            gemm_tc<1, 1><<<grd3, 256, SM3>>>(h2h, h2l, w3h, w3l, b3,
                                              k[s], nullptr, nullptr, HH, DD, ep);
        }
    }
}

// round 15
// speedup vs baseline: 1.3912x; 1.0369x over previous
#include <cuda_runtime.h>
#include <cuda_fp16.h>
#include <cstdint>
#include <cstddef>

// ---------------------------------------------------------------------------
// NeuralODE Dopri5. GEMMs: mma.sync m16n8k16 FP16 (2xFP16 split: X=Xh+Xl;
// Ah·Wh + Ah·Wl + Al·Wh, fp32 accum). ALL operands pre-split fp16 hi/lo in
// gmem -> full cp.async 4-stage pipeline, wait_group 2, one barrier/stage,
// ldmatrix fragments. R15: compile-time K (fully unrolled stage loop) +
// epilogue operand prefetch hidden under the mainloop.
// ---------------------------------------------------------------------------

#define BB 1024
#define DD 256
#define HH 512
#define N_STEPS 40
#define HSTEP 0.25f

__device__ float  g_y [BB * DD];          // fp32 RK state
__device__ float  g_k [6][BB * DD];       // fp32 stage derivatives
__device__ __half g_yh  [BB * DD], g_yl  [BB * DD];
__device__ __half g_cmh [BB * DD], g_cml [BB * DD];
__device__ __half g_h1h [BB * HH], g_h1l [BB * HH];
__device__ __half g_h2h [BB * HH], g_h2l [BB * HH];
__device__ __half g_W1hi[HH * DD], g_W1lo[HH * DD];
__device__ __half g_W2hi[HH * HH], g_W2lo[HH * HH];
__device__ __half g_W3hi[DD * HH], g_W3lo[DD * HH];

struct Epi {
    const float* yin;
    const float* ks[4];
    float        cks[4];
    int          nks;
    float        cself;
    __half*      auxh;
    __half*      auxl;
    float*       auxfp;
    float*       emit;
    int          t;
};

// ----------------------------- helpers -------------------------------------
__device__ __forceinline__ uint32_t smem_u32(const void* p) {
    uint32_t a;
    asm("{ .reg .u64 t; cvta.to.shared.u64 t, %1; cvt.u32.u64 %0, t; }"
        : "=r"(a) : "l"(p));
    return a;
}
__device__ __forceinline__ uint32_t packh2(__half a, __half b) {
    __half2 t = __halves2half2(a, b);
    return *reinterpret_cast<uint32_t*>(&t);
}
__device__ __forceinline__ void cp16(uint32_t d, const void* s) {
    asm volatile("cp.async.cg.shared.global [%0], [%1], 16;"
                 :: "r"(d), "l"(s) : "memory");
}
__device__ __forceinline__ void cp_commit() {
    asm volatile("cp.async.commit_group;" ::: "memory");
}
__device__ __forceinline__ void cp_wait2() {
    asm volatile("cp.async.wait_group 2;" ::: "memory");
}
__device__ __forceinline__ void ldm4(uint32_t* r, uint32_t addr) {
    asm volatile("ldmatrix.sync.aligned.m8n8.x4.shared.b16 {%0,%1,%2,%3}, [%4];"
                 : "=r"(r[0]), "=r"(r[1]), "=r"(r[2]), "=r"(r[3]) : "r"(addr));
}
__device__ __forceinline__ void mma16(float* d, const uint32_t* a,
                                      uint32_t b0, uint32_t b1) {
    asm volatile(
        "mma.sync.aligned.m16n8k16.row.col.f32.f16.f16.f32 "
        "{%0,%1,%2,%3}, {%4,%5,%6,%7}, {%8,%9}, {%0,%1,%2,%3};"
        : "+f"(d[0]), "+f"(d[1]), "+f"(d[2]), "+f"(d[3])
        : "r"(a[0]), "r"(a[1]), "r"(a[2]), "r"(a[3]), "r"(b0), "r"(b1));
}

// ---------------------------------------------------------------------------
// GEMM: out = act(A @ W^T + bias). 256 threads, warp grid 2(M) x 4(N),
// warp tile (16*MT) x 16, CTA tile (32*MT) x 64. BK=64, S=K/64 compile-time
// (fully unrolled), 4 smem stage buffers, all operands via cp.async,
// wait_group 2, one __syncthreads + one commit per stage.
// Smem rows 128B (64 fp16), XOR swizzle: 16B-chunk ^= (row&7).
// Stage: Ahi[AB] Alo[AB] Whi[8192] Wlo[8192], AB = BM*128.
// MODE 0: relu, outputs split fp16 (Chi/Clo).
// MODE 1: fp32 store + fused RK combine; y/k operands prefetched pre-mainloop.
// ---------------------------------------------------------------------------
template<int K, int MT, int MODE>
__global__ __launch_bounds__(256, 1)
void gemm_tc(const __half* __restrict__ Ahi, const __half* __restrict__ Alo,
             const __half* __restrict__ Whi, const __half* __restrict__ Wlo,
             const float* __restrict__ bias,
             float* __restrict__ C, __half* __restrict__ Chi,
             __half* __restrict__ Clo, int N, Epi ep)
{
    constexpr int BM  = 32 * MT;
    constexpr int TPR = 256 / BM;
    constexpr int CPT = 8 / TPR;
    constexpr int S   = K / 64;
    constexpr uint32_t AB = (uint32_t)BM * 128;
    constexpr uint32_t WB = 64 * 128;
    constexpr uint32_t WOFFS = 2 * AB;
    constexpr uint32_t STRIDE = 2 * AB + 2 * WB;

    extern __shared__ float smem[];
    const uint32_t sb = smem_u32(smem);
    const int tid  = threadIdx.x;
    const int warp = tid >> 5, lane = tid & 31;
    const int wM = warp >> 2, wN = warp & 3;
    const int g = lane >> 2, c = lane & 3;
    const int m0 = blockIdx.y * BM, n0 = blockIdx.x * 64;

    // loader geometry (base pointers hoisted; stage advances by 64 elements)
    const int arw  = tid / TPR;
    const int akc0 = (tid % TPR) * CPT;
    const int wrw  = tid >> 2;
    const int wkc0 = (tid & 3) * 2;
    const __half* aSrcH = Ahi + (size_t)(m0 + arw) * K + akc0 * 8;
    const __half* aSrcL = Alo + (size_t)(m0 + arw) * K + akc0 * 8;
    const __half* wSrcH = Whi + (size_t)(n0 + wrw) * K + wkc0 * 8;
    const __half* wSrcL = Wlo + (size_t)(n0 + wrw) * K + wkc0 * 8;
    const uint32_t aDst0 = (uint32_t)arw * 128;
    const uint32_t wDst0 = WOFFS + (uint32_t)wrw * 128;

    // ldmatrix geometry
    const int quad = lane >> 3, l8 = lane & 7;
    const uint32_t aqs = (uint32_t)(quad >> 1);
    const uint32_t bqs = (uint32_t)(quad & 1);
    uint32_t aoffA[MT];
    #pragma unroll
    for (int i = 0; i < MT; i++)
        aoffA[i] = (uint32_t)(wM * 16 * MT + i * 16 + ((quad & 1) << 3) + l8) * 128;
    const uint32_t boffB = WOFFS
        + (uint32_t)(wN * 16 + ((quad >> 1) << 3) + l8) * 128;

    auto cpStage = [&](int s, int buf) {
        const uint32_t b0 = sb + (uint32_t)buf * STRIDE;
        #pragma unroll
        for (int q = 0; q < CPT; q++) {
            const int kc = akc0 + q;
            const uint32_t d = b0 + aDst0 + (uint32_t)((kc ^ (arw & 7)) << 4);
            cp16(d,      aSrcH + s * 64 + q * 8);
            cp16(d + AB, aSrcL + s * 64 + q * 8);
        }
        #pragma unroll
        for (int q = 0; q < 2; q++) {
            const int kc = wkc0 + q;
            const uint32_t d = b0 + wDst0 + (uint32_t)((kc ^ (wrw & 7)) << 4);
            cp16(d,      wSrcH + s * 64 + q * 8);
            cp16(d + WB, wSrcL + s * 64 + q * 8);
        }
        cp_commit();
    };

    float acc[MT][2][4];
    #pragma unroll
    for (int i = 0; i < MT; i++)
        #pragma unroll
        for (int nt = 0; nt < 2; nt++)
            #pragma unroll
            for (int q = 0; q < 4; q++) acc[i][nt][q] = 0.0f;

    // prologue: 3 stages in flight
    cpStage(0, 0);
    cpStage(1, 1);
    cpStage(2, 2);

    // ---- epilogue operand prefetch (hidden under the mainloop) ----
    float2 pre_y[MT][2][2];
    float2 pre_k[4][MT][2][2];
    float  bpre[2][2];
    if (MODE == 1) {
        #pragma unroll
        for (int nt = 0; nt < 2; nt++) {
            const int col = n0 + wN * 16 + nt * 8 + 2 * c;
            bpre[nt][0] = bias[col];
            bpre[nt][1] = bias[col + 1];
            #pragma unroll
            for (int i = 0; i < MT; i++) {
                #pragma unroll
                for (int hh = 0; hh < 2; hh++) {
                    const int row = m0 + wM * 16 * MT + i * 16 + g + 8 * hh;
                    const size_t idx = (size_t)row * N + col;
                    pre_y[i][nt][hh] = *(const float2*)(ep.yin + idx);
                    for (int t = 0; t < ep.nks; t++)
                        pre_k[t][i][nt][hh] = *(const float2*)(ep.ks[t] + idx);
                }
            }
        }
    }

    // ---- fully unrolled mainloop ----
    #pragma unroll
    for (int s = 0; s < S; s++) {
        cp_wait2();
        __syncthreads();
        if (s + 3 < S) cpStage(s + 3, (s + 3) & 3);
        else           cp_commit();

        const uint32_t base = sb + (uint32_t)(s & 3) * STRIDE;
        uint32_t ah[2][MT][4], al[2][MT][4], bh[2][4], bl[2][4];

        auto ldfrag = [&](int j, int fb) {
            const uint32_t colA = (uint32_t)(((2 * j + aqs) ^ l8) << 4);
            const uint32_t colB = (uint32_t)(((2 * j + bqs) ^ l8) << 4);
            #pragma unroll
            for (int i = 0; i < MT; i++) {
                ldm4(ah[fb][i], base + aoffA[i] + colA);
                ldm4(al[fb][i], base + AB + aoffA[i] + colA);
            }
            ldm4(bh[fb], base + boffB + colB);
            ldm4(bl[fb], base + WB + boffB + colB);
        };

        ldfrag(0, 0);
        #pragma unroll
        for (int j = 0; j < 4; j++) {
            const int fb = j & 1;
            if (j < 3) ldfrag(j + 1, fb ^ 1);
            #pragma unroll
            for (int i = 0; i < MT; i++) {
                mma16(acc[i][0], ah[fb][i], bh[fb][0], bh[fb][1]);
                mma16(acc[i][1], ah[fb][i], bh[fb][2], bh[fb][3]);
                mma16(acc[i][0], ah[fb][i], bl[fb][0], bl[fb][1]);
                mma16(acc[i][1], ah[fb][i], bl[fb][2], bl[fb][3]);
                mma16(acc[i][0], al[fb][i], bh[fb][0], bh[fb][1]);
                mma16(acc[i][1], al[fb][i], bh[fb][2], bh[fb][3]);
            }
        }
    }

    // ---- epilogue ----
    #pragma unroll
    for (int i = 0; i < MT; i++) {
        #pragma unroll
        for (int nt = 0; nt < 2; nt++) {
            const int col = n0 + wN * 16 + nt * 8 + 2 * c;
            const int row0 = m0 + wM * 16 * MT + i * 16 + g;
            float b0v, b1v;
            if (MODE == 1) { b0v = bpre[nt][0]; b1v = bpre[nt][1]; }
            else           { b0v = bias[col];   b1v = bias[col + 1]; }
            #pragma unroll
            for (int hh = 0; hh < 2; hh++) {
                const int row = row0 + 8 * hh;
                float v0 = acc[i][nt][2 * hh + 0] + b0v;
                float v1 = acc[i][nt][2 * hh + 1] + b1v;
                const size_t idx = (size_t)row * N + col;
                if (MODE == 0) {
                    v0 = fmaxf(v0, 0.0f); v1 = fmaxf(v1, 0.0f);
                    __half h0 = __float2half_rn(v0), h1 = __float2half_rn(v1);
                    *reinterpret_cast<uint32_t*>(Chi + idx) = packh2(h0, h1);
                    *reinterpret_cast<uint32_t*>(Clo + idx) = packh2(
                        __float2half_rn(v0 - __half2float(h0)),
                        __float2half_rn(v1 - __half2float(h1)));
                } else {
                    *(float2*)(C + idx) = make_float2(v0, v1);
                    float a0 = pre_y[i][nt][hh].x + ep.cself * v0;
                    float a1 = pre_y[i][nt][hh].y + ep.cself * v1;
                    for (int t = 0; t < ep.nks; t++) {
                        a0 += ep.cks[t] * pre_k[t][i][nt][hh].x;
                        a1 += ep.cks[t] * pre_k[t][i][nt][hh].y;
                    }
                    __half h0 = __float2half_rn(a0), h1 = __float2half_rn(a1);
                    *reinterpret_cast<uint32_t*>(ep.auxh + idx) = packh2(h0, h1);
                    *reinterpret_cast<uint32_t*>(ep.auxl + idx) = packh2(
                        __float2half_rn(a0 - __half2float(h0)),
                        __float2half_rn(a1 - __half2float(h1)));
                    if (ep.auxfp)
                        *(float2*)(ep.auxfp + idx) = make_float2(a0, a1);
                    if (ep.emit) {
                        const size_t o = (size_t)row * (10 * DD) + (size_t)ep.t * DD + col;
                        *(float2*)(ep.emit + o) = make_float2(a0, a1);
                    }
                }
            }
        }
    }
}

// Split fp32 X into fp16 hi/lo parts
__global__ void wsplit_kernel(const float* __restrict__ X,
                              __half* __restrict__ hi, __half* __restrict__ lo,
                              int n)
{
    int i = blockIdx.x * blockDim.x + threadIdx.x;
    if (i < n) {
        float x = X[i];
        __half h = __float2half_rn(x);
        hi[i] = h;
        lo[i] = __float2half_rn(x - __half2float(h));
    }
}

extern "C" void kernel_launch(void* const* d_in, const int* in_sizes, int n_in,
                              void* d_out, int out_size)
{
    (void)in_sizes; (void)n_in; (void)out_size;
    const float* x0 = (const float*)d_in[0];
    // d_in[1] is T (int32, always 11) — baked into the graph.
    const float* W1 = (const float*)d_in[2];
    const float* b1 = (const float*)d_in[3];
    const float* W2 = (const float*)d_in[4];
    const float* b2 = (const float*)d_in[5];
    const float* W3 = (const float*)d_in[6];
    const float* b3 = (const float*)d_in[7];
    float* out = (float*)d_out;

    float *y, *kbase;
    __half *yh, *yl, *cmh, *cml, *h1h, *h1l, *h2h, *h2l;
    __half *w1h, *w1l, *w2h, *w2l, *w3h, *w3l;
    cudaGetSymbolAddress((void**)&y,     g_y);
    cudaGetSymbolAddress((void**)&kbase, g_k);
    cudaGetSymbolAddress((void**)&yh,    g_yh);
    cudaGetSymbolAddress((void**)&yl,    g_yl);
    cudaGetSymbolAddress((void**)&cmh,   g_cmh);
    cudaGetSymbolAddress((void**)&cml,   g_cml);
    cudaGetSymbolAddress((void**)&h1h,   g_h1h);
    cudaGetSymbolAddress((void**)&h1l,   g_h1l);
    cudaGetSymbolAddress((void**)&h2h,   g_h2h);
    cudaGetSymbolAddress((void**)&h2l,   g_h2l);
    cudaGetSymbolAddress((void**)&w1h,   g_W1hi);
    cudaGetSymbolAddress((void**)&w1l,   g_W1lo);
    cudaGetSymbolAddress((void**)&w2h,   g_W2hi);
    cudaGetSymbolAddress((void**)&w2l,   g_W2lo);
    cudaGetSymbolAddress((void**)&w3h,   g_W3hi);
    cudaGetSymbolAddress((void**)&w3l,   g_W3lo);
    float* k[6];
    for (int j = 0; j < 6; j++) k[j] = (float*)kbase + (size_t)j * BB * DD;

    // 4 stage buffers of (2*AB + 2*WB)
    const int SM12 = 4 * (2 * 64 * 128 + 2 * 64 * 128);   // MT=2: 131072
    const int SM3  = 4 * (2 * 32 * 128 + 2 * 64 * 128);   // MT=1: 98304
    cudaFuncSetAttribute((const void*)&gemm_tc<256, 2, 0>,
                         cudaFuncAttributeMaxDynamicSharedMemorySize, SM12);
    cudaFuncSetAttribute((const void*)&gemm_tc<512, 2, 0>,
                         cudaFuncAttributeMaxDynamicSharedMemorySize, SM12);
    cudaFuncSetAttribute((const void*)&gemm_tc<512, 1, 1>,
                         cudaFuncAttributeMaxDynamicSharedMemorySize, SM3);

    // y = x0[:,0,:]; split to fp16 hi/lo
    cudaMemcpyAsync(y, x0, sizeof(float) * BB * DD, cudaMemcpyDeviceToDevice);
    wsplit_kernel<<<(BB * DD + 255) / 256, 256>>>(x0, yh, yl, BB * DD);
    wsplit_kernel<<<(HH * DD + 255) / 256, 256>>>(W1, w1h, w1l, HH * DD);
    wsplit_kernel<<<(HH * HH + 255) / 256, 256>>>(W2, w2h, w2l, HH * HH);
    wsplit_kernel<<<(DD * HH + 255) / 256, 256>>>(W3, w3h, w3l, DD * HH);

    // Dopri5 tableau
    const double A2[] = {1.0/5.0};
    const double A3[] = {3.0/40.0, 9.0/40.0};
    const double A4[] = {44.0/45.0, -56.0/15.0, 32.0/9.0};
    const double A5[] = {19372.0/6561.0, -25360.0/2187.0, 64448.0/6561.0, -212.0/729.0};
    const double A6[] = {9017.0/3168.0, -355.0/33.0, 46732.0/5247.0, 49.0/176.0, -5103.0/18656.0};
    const double* Arows[5] = {A2, A3, A4, A5, A6};

    const dim3 grd1(HH / 64, BB / 64);   // 8 x 16 = 128 CTAs
    const dim3 grd3(DD / 64, BB / 32);   // 4 x 32 = 128 CTAs

    Epi enone = {};

    for (int step = 0; step < N_STEPS; step++) {
        for (int s = 0; s < 6; s++) {
            const __half* Ah = (s == 0) ? yh : cmh;
            const __half* Al = (s == 0) ? yl : cml;
            gemm_tc<256, 2, 0><<<grd1, 256, SM12>>>(Ah, Al, w1h, w1l, b1,
                                                    nullptr, h1h, h1l, HH, enone);
            gemm_tc<512, 2, 0><<<grd1, 256, SM12>>>(h1h, h1l, w2h, w2l, b2,
                                                    nullptr, h2h, h2l, HH, enone);

            Epi ep = {};
            ep.yin = y;
            if (s < 5) {
                const double* row = Arows[s];
                ep.nks = s;
                for (int j = 0; j < s; j++) {
                    ep.ks[j]  = k[j];
                    ep.cks[j] = (float)((double)HSTEP * row[j]);
                }
                ep.cself = (float)((double)HSTEP * row[s]);
                ep.auxh  = cmh;
                ep.auxl  = cml;
                ep.auxfp = nullptr;
                ep.emit  = nullptr;
                ep.t     = 0;
            } else {
                ep.nks = 4;
                ep.ks[0] = k[0]; ep.cks[0] = (float)((double)HSTEP * (35.0 / 384.0));
                ep.ks[1] = k[2]; ep.cks[1] = (float)((double)HSTEP * (500.0 / 1113.0));
                ep.ks[2] = k[3]; ep.cks[2] = (float)((double)HSTEP * (125.0 / 192.0));
                ep.ks[3] = k[4]; ep.cks[3] = (float)((double)HSTEP * (-2187.0 / 6784.0));
                ep.cself = (float)((double)HSTEP * (11.0 / 84.0));
                ep.auxh  = yh;
                ep.auxl  = yl;
                ep.auxfp = y;
                ep.emit  = ((step & 3) == 3) ? out : nullptr;
                ep.t     = step >> 2;
            }
            gemm_tc<512, 1, 1><<<grd3, 256, SM3>>>(h2h, h2l, w3h, w3l, b3,
                                                   k[s], nullptr, nullptr, DD, ep);
        }
    }
}